// round 17
// baseline (speedup 1.0000x reference)
#include <cuda_runtime.h>
#include <cuda_fp16.h>
#include <math.h>

#define BB   4
#define NN   10000
#define EE   100000
#define CIN  16
#define NF   128
#define WN   384
#define OUTD 40
#define MROWS (BB*EE)            // 400000
#define ALPHA_C 0.25f
#define BN_EPS_C 1e-5f
#define M_TOT 40000.0f
#define KPAD 136                 // fp16 smem row stride (272B, ldmatrix conflict-free)
#define EWP  134                 // fp16 sEw row stride (halfs)
#define OFF_A  0                 // 128*KPAD halfs = 34816 B
#define OFF_W  34816             // 128*KPAD halfs = 34816 B
#define OFF_EW 69632             // 128*EWP halfs = 34304 B
#define SMEM_BYTES 103936        // -> 2 CTAs/SM

// ---------------- device scratch ---------------------------------------------
__device__ float g_xnew[BB*NN*CIN];
__device__ float g_agg[BB*NN*OUTD];
__device__ float g_cnt[NN];
__device__ float g_cntinv[NN];
__device__ float g_sum[OUTD];
__device__ float g_sumsq[OUTD];
__device__ __align__(16) __half g_w1t[NF*NF];   // [n][k] transposed fp16
__device__ __align__(16) __half g_w2t[WN*NF];   // [n][k] transposed fp16

// ---------------- init: zero scratch + weight prep + FFT time mixing ---------
__global__ void init_kernel(const float* __restrict__ x,
                            const float* __restrict__ wr,
                            const float* __restrict__ wi,
                            const float* __restrict__ w1,
                            const float* __restrict__ w2) {
    __shared__ float sWr[CIN][CIN];
    __shared__ float sWi[CIN][CIN];
    int t = threadIdx.x;
    {   // sum over MODES=2: tc_w* shape (16,16,2)
        int i = t >> 4, o = t & 15;
        sWr[i][o] = wr[i*32 + o*2 + 0] + wr[i*32 + o*2 + 1];
        sWi[i][o] = wi[i*32 + o*2 + 0] + wi[i*32 + o*2 + 1];
    }
    __syncthreads();
    int idx = blockIdx.x * blockDim.x + t;

    if (idx < BB*NN*OUTD) g_agg[idx] = 0.0f;
    if (idx < NN)         g_cnt[idx] = 0.0f;
    if (idx < OUTD) { g_sum[idx] = 0.0f; g_sumsq[idx] = 0.0f; }
    if (idx < NF*NF) {
        int n = idx / NF, k = idx % NF;
        g_w1t[idx] = __float2half_rn(w1[k*NF + n]);
    }
    if (idx < WN*NF) {
        int n = idx / NF, k = idx % NF;
        g_w2t[idx] = __float2half_rn(w2[k*WN + n]);
    }
    if (idx < NN*CIN) {
        int n = idx >> 4, o = idx & 15;
        float x0r = 0.f, re1 = 0.f, im1 = 0.f;
        #pragma unroll
        for (int i = 0; i < CIN; i++) {
            float a0 = x[(0*NN + n)*CIN + i];
            float a1 = x[(1*NN + n)*CIN + i];
            float a2 = x[(2*NN + n)*CIN + i];
            float a3 = x[(3*NN + n)*CIN + i];
            float S = a0 + a1 + a2 + a3;
            float P = a0 - a2;
            float Q = a3 - a1;
            float wrv = sWr[i][o], wiv = sWi[i][o];
            x0r += S * wrv;
            re1 += P * wrv - Q * wiv;
            im1 += P * wiv + Q * wrv;
        }
        g_xnew[(0*NN + n)*CIN + o] = 0.25f*(x0r + 2.f*re1);
        g_xnew[(1*NN + n)*CIN + o] = 0.25f*(x0r - 2.f*im1);
        g_xnew[(2*NN + n)*CIN + o] = 0.25f*(x0r - 2.f*re1);
        g_xnew[(3*NN + n)*CIN + o] = 0.25f*(x0r + 2.f*im1);
    }
}

// ---------------- per-node in-degree -----------------------------------------
__global__ void count_kernel(const int* __restrict__ eidx) {
    int e = blockIdx.x * blockDim.x + threadIdx.x;
    if (e < EE) atomicAdd(&g_cnt[eidx[EE + e]], 1.0f);
}

// ---------------- helpers -----------------------------------------------------
__device__ __forceinline__ void mma_f16(float* c, const unsigned* a, const unsigned* b) {
    asm volatile(
        "mma.sync.aligned.m16n8k16.row.col.f32.f16.f16.f32 "
        "{%0,%1,%2,%3}, {%4,%5,%6,%7}, {%8,%9}, {%0,%1,%2,%3};\n"
        : "+f"(c[0]), "+f"(c[1]), "+f"(c[2]), "+f"(c[3])
        : "r"(a[0]), "r"(a[1]), "r"(a[2]), "r"(a[3]), "r"(b[0]), "r"(b[1]));
}
__device__ __forceinline__ void ldmat4(unsigned* a, const __half* p) {
    unsigned addr = (unsigned)__cvta_generic_to_shared(p);
    asm volatile("ldmatrix.sync.aligned.m8n8.x4.shared.b16 {%0,%1,%2,%3}, [%4];"
                 : "=r"(a[0]), "=r"(a[1]), "=r"(a[2]), "=r"(a[3]) : "r"(addr));
}
__device__ __forceinline__ unsigned packh2(float a, float b) {
    __half2 t;
    t.x = __float2half_rn(a);
    t.y = __float2half_rn(b);
    return *reinterpret_cast<unsigned*>(&t);
}
__device__ __forceinline__ void cpa16(void* dst, const void* src) {
    unsigned d = (unsigned)__cvta_generic_to_shared(dst);
    asm volatile("cp.async.cg.shared.global [%0], [%1], 16;" :: "r"(d), "l"(src));
}
#define CP_COMMIT asm volatile("cp.async.commit_group;")
#define CP_WAIT0  asm volatile("cp.async.wait_group 0;" ::: "memory")

// single-term fp16 GEMM (proven R9): acc += A@W^T  (M=128, N=128, K=128)
__device__ __forceinline__ void gemm_f16(
    const __half* __restrict__ sA, const __half* __restrict__ sW,
    int warp, int lane, float acc[8][2][4])
{
    const __half* Arow = sA + (lane & 15)*KPAD + (lane >> 4)*8;
    const __half* Wb = sW + (warp*16 + (lane >> 2))*KPAD + (lane & 3)*2;
    #pragma unroll
    for (int k0 = 0; k0 < 128; k0 += 16) {
        unsigned b0[2], b1[2];
        b0[0] = *(const unsigned*)&Wb[k0];
        b0[1] = *(const unsigned*)&Wb[k0 + 8];
        b1[0] = *(const unsigned*)&Wb[8*KPAD + k0];
        b1[1] = *(const unsigned*)&Wb[8*KPAD + k0 + 8];
        #pragma unroll
        for (int mt = 0; mt < 8; mt++) {
            unsigned a[4];
            ldmat4(a, Arow + mt*16*KPAD + k0);
            mma_f16(acc[mt][0], a, b0);
            mma_f16(acc[mt][1], a, b1);
        }
    }
}

// ---------------- fused: GEMM1 + relu + GEMM2 + message + scatter ------------
// (unchanged from R15 winner)
__global__ __launch_bounds__(256, 2)
void fused_kernel(const float* __restrict__ ea,  const float* __restrict__ b1g,
                  const float* __restrict__ b2g, const int* __restrict__ eidx,
                  const float* __restrict__ esh)
{
    extern __shared__ char smem_raw[];
    __half* sA  = (__half*)(smem_raw + OFF_A);     // 128 x KPAD fp16
    __half* sW  = (__half*)(smem_raw + OFF_W);     // 128 x KPAD fp16
    __half* sEw = (__half*)(smem_raw + OFF_EW);    // 128 x EWP fp16

    const int tid  = threadIdx.x;
    const int warp = tid >> 5, lane = tid & 31;
    const int row0 = blockIdx.x * 128;

    // ---- prefetch W1 via cp.async (overlaps A gather) ----
    #pragma unroll
    for (int t = 0; t < 8; t++) {
        int idx = tid + t * 256;
        int n = idx >> 4, q = (idx & 15) << 3;
        cpa16(&sW[n*KPAD + q], &g_w1t[n*NF + q]);
    }
    CP_COMMIT;

    // ---- load A tile (128x128 f32 -> fp16) ----
    #pragma unroll
    for (int t = 0; t < 16; t++) {
        int idx = tid + t * 256;           // 0..4095 float4s
        int r = idx >> 5, q = (idx & 31) << 2;
        float4 v = *(const float4*)&ea[(size_t)(row0 + r)*NF + q];
        uint2 u = make_uint2(packh2(v.x, v.y), packh2(v.z, v.w));
        *(uint2*)&sA[r*KPAD + q] = u;
    }
    CP_WAIT0;
    __syncthreads();

    // ---- GEMM1: H = relu(A@W1 + b1) ----
    float acc[8][2][4];
    {
        int colb = warp*16 + (lane & 3)*2;
        #pragma unroll
        for (int nt = 0; nt < 2; nt++) {
            float bc0 = b1g[colb + nt*8], bc1 = b1g[colb + nt*8 + 1];
            #pragma unroll
            for (int mt = 0; mt < 8; mt++) {
                acc[mt][nt][0] = bc0; acc[mt][nt][1] = bc1;
                acc[mt][nt][2] = bc0; acc[mt][nt][3] = bc1;
            }
        }
    }
    gemm_f16(sA, sW, warp, lane, acc);
    __syncthreads();   // done reading sA and sW

    // ---- prefetch W2 chunk 0 (overlaps re-split + metadata) ----
    #pragma unroll
    for (int t = 0; t < 8; t++) {
        int idx = tid + t * 256;
        int n = idx >> 4, q = (idx & 15) << 3;
        cpa16(&sW[n*KPAD + q], &g_w2t[n*NF + q]);
    }
    CP_COMMIT;

    // ---- relu -> fp16 H back into sA ----
    {
        int c0 = warp*16 + (lane & 3)*2;
        int r0 = lane >> 2;
        #pragma unroll
        for (int mt = 0; mt < 8; mt++) {
            #pragma unroll
            for (int nt = 0; nt < 2; nt++) {
                int col = c0 + nt*8;
                #pragma unroll
                for (int half = 0; half < 2; half++) {
                    int row = mt*16 + r0 + half*8;
                    float h0 = fmaxf(acc[mt][nt][half*2 + 0], 0.f);
                    float h1 = fmaxf(acc[mt][nt][half*2 + 1], 0.f);
                    *(unsigned*)&sA[row*KPAD + col] = packh2(h0, h1);
                }
            }
        }
    }

    // ---- per-edge metadata (2 threads per row) ----
    const int r_e = tid >> 1, l = tid & 1;
    const int grow = row0 + r_e;
    const int b = grow / EE;
    const int e = grow - b*EE;
    const int src = eidx[e];
    const int dst = eidx[EE + e];
    const float4 sh = *(const float4*)&esh[(size_t)grow*4];
    float xg[CIN];
    {
        const float4* xgp = (const float4*)&g_xnew[((size_t)b*NN + src)*CIN];
        #pragma unroll
        for (int t4 = 0; t4 < 4; t4++) {
            float4 v = xgp[t4];
            xg[t4*4+0] = v.x; xg[t4*4+1] = v.y; xg[t4*4+2] = v.z; xg[t4*4+3] = v.w;
        }
    }
    float o0[8] = {0,0,0,0,0,0,0,0};
    float d1[4] = {0,0,0,0};

    CP_WAIT0;
    __syncthreads();   // H visible + W2 ch0 staged

    // ---- GEMM2 in 3 N-chunks of 128, fused message contraction ----
    #pragma unroll 1
    for (int ch = 0; ch < 3; ch++) {
        {
            int colb = ch*128 + warp*16 + (lane & 3)*2;
            #pragma unroll
            for (int nt = 0; nt < 2; nt++) {
                float bc0 = b2g[colb + nt*8], bc1 = b2g[colb + nt*8 + 1];
                #pragma unroll
                for (int mt = 0; mt < 8; mt++) {
                    acc[mt][nt][0] = bc0; acc[mt][nt][1] = bc1;
                    acc[mt][nt][2] = bc0; acc[mt][nt][3] = bc1;
                }
            }
        }
        gemm_f16(sA, sW, warp, lane, acc);
        __syncthreads();   // done reading sW; prev contraction long done

        // prefetch next W2 chunk into sW (overlaps sEw write + contraction)
        if (ch < 2) {
            #pragma unroll
            for (int t = 0; t < 8; t++) {
                int idx = tid + t * 256;
                int n = idx >> 4, q = (idx & 15) << 3;
                cpa16(&sW[n*KPAD + q], &g_w2t[(size_t)((ch+1)*128 + n)*NF + q]);
            }
            CP_COMMIT;
        }

        // write acc -> sEw (packed fp16)
        {
            int c0 = warp*16 + (lane & 3)*2;
            int r0 = lane >> 2;
            #pragma unroll
            for (int mt = 0; mt < 8; mt++) {
                #pragma unroll
                for (int nt = 0; nt < 2; nt++) {
                    int col = c0 + nt*8;
                    *(unsigned*)&sEw[(mt*16 + r0    )*EWP + col] =
                        packh2(acc[mt][nt][0], acc[mt][nt][1]);
                    *(unsigned*)&sEw[(mt*16 + r0 + 8)*EWP + col] =
                        packh2(acc[mt][nt][2], acc[mt][nt][3]);
                }
            }
        }
        __syncthreads();

        // message partial accumulation from this ew chunk (half2 reads)
        const __half2* er2 = (const __half2*)&sEw[r_e*EWP];
        if (ch == 0) {
            #pragma unroll
            for (int op = 0; op < 4; op++) {
                #pragma unroll
                for (int i = 0; i < 8; i++) {
                    float2 f = __half22float2(er2[i*8 + l*4 + op]);
                    o0[op*2]     += xg[i] * f.x;
                    o0[op*2 + 1] += xg[i] * f.y;
                }
            }
        } else if (ch == 1) {
            #pragma unroll
            for (int op = 0; op < 4; op++) {
                #pragma unroll
                for (int i = 0; i < 8; i++) {
                    float2 f = __half22float2(er2[i*8 + l*4 + op]);
                    o0[op*2]     += xg[i+8] * f.x;
                    o0[op*2 + 1] += xg[i+8] * f.y;
                }
            }
        } else {
            #pragma unroll
            for (int op = 0; op < 2; op++) {
                #pragma unroll
                for (int i = 0; i < 16; i++) {
                    float2 f = __half22float2(er2[i*4 + l*2 + op]);
                    d1[op*2]     += xg[i] * f.x;
                    d1[op*2 + 1] += xg[i] * f.y;
                }
            }
        }
        if (ch < 2) { CP_WAIT0; }
        __syncthreads();   // contraction done; sW ready for next chunk
    }

    // ---- scatter ----
    float* aggp = &g_agg[((size_t)b*NN + dst)*OUTD];
    float s0 = ALPHA_C * sh.x;
    #pragma unroll
    for (int oi = 0; oi < 8; oi++)
        atomicAdd(&aggp[l*8 + oi], s0 * o0[oi]);
    #pragma unroll
    for (int oi = 0; oi < 4; oi++) {
        int cch = l*4 + oi;
        float v = ALPHA_C * d1[oi];
        atomicAdd(&aggp[16 + cch*3 + 0], v * sh.y);
        atomicAdd(&aggp[16 + cch*3 + 1], v * sh.z);
        atomicAdd(&aggp[16 + cch*3 + 2], v * sh.w);
    }
}

// ---------------- BN stats: read-only pass, 1 row per thread -----------------
// Also emits g_cntinv for norm. No g_agg write-back (norm recomputes agg*inv,
// identical value / identical rounding).
__global__ void stats_kernel() {
    int row = blockIdx.x * blockDim.x + threadIdx.x;
    float s[OUTD], q[OUTD];
    float inv = 0.f;
    if (row < BB*NN) {
        int n = row % NN;
        inv = 1.0f / fmaxf(g_cnt[n], 1.0f);
        if (row < NN) g_cntinv[row] = inv;
    }
    if (row < BB*NN) {
        const float4* p = (const float4*)&g_agg[row*OUTD];
        #pragma unroll
        for (int t = 0; t < 10; t++) {
            float4 a = p[t];
            a.x *= inv; a.y *= inv; a.z *= inv; a.w *= inv;
            s[t*4+0] = a.x; q[t*4+0] = a.x*a.x;
            s[t*4+1] = a.y; q[t*4+1] = a.y*a.y;
            s[t*4+2] = a.z; q[t*4+2] = a.z*a.z;
            s[t*4+3] = a.w; q[t*4+3] = a.w*a.w;
        }
    } else {
        #pragma unroll
        for (int c = 0; c < OUTD; c++) { s[c] = 0.f; q[c] = 0.f; }
    }
    #pragma unroll
    for (int c = 0; c < OUTD; c++) {
        float sv = s[c], qv = q[c];
        #pragma unroll
        for (int off = 16; off > 0; off >>= 1) {
            sv += __shfl_down_sync(0xffffffffu, sv, off);
            qv += __shfl_down_sync(0xffffffffu, qv, off);
        }
        if ((threadIdx.x & 31) == 0) {
            atomicAdd(&g_sum[c],   sv);
            atomicAdd(&g_sumsq[c], qv);
        }
    }
}

// ---------------- batchnorm normalize (per-block channel precompute) ---------
__global__ void norm_kernel(float* __restrict__ out,
                            const float* __restrict__ gamma,
                            const float* __restrict__ beta) {
    __shared__ float sc[OUTD], sf[OUTD];
    int tid = threadIdx.x;
    if (tid < OUTD) {
        const float invM = 1.0f / M_TOT;
        float mu  = g_sum[tid] * invM;
        float var = g_sumsq[tid] * invM - mu*mu;
        float rs  = rsqrtf(var + BN_EPS_C);
        float scv = rs * gamma[tid];
        sc[tid] = scv;
        sf[tid] = beta[tid] - mu * scv;
    }
    __syncthreads();
    int i = blockIdx.x * blockDim.x + tid;
    if (i >= BB*NN*OUTD) return;
    int row = i / OUTD;
    int c = i - row*OUTD;
    int n = row % NN;
    out[i] = g_agg[i] * g_cntinv[n] * sc[c] + sf[c];
}

// ---------------- launch ------------------------------------------------------
extern "C" void kernel_launch(void* const* d_in, const int* in_sizes, int n_in,
                              void* d_out, int out_size) {
    const float* x     = (const float*)d_in[0];
    const int*   eidx  = (const int*)  d_in[1];
    const float* ea    = (const float*)d_in[2];
    const float* esh   = (const float*)d_in[3];
    const float* wr    = (const float*)d_in[4];
    const float* wi    = (const float*)d_in[5];
    const float* w1    = (const float*)d_in[6];
    const float* b1    = (const float*)d_in[7];
    const float* w2    = (const float*)d_in[8];
    const float* b2    = (const float*)d_in[9];
    const float* gamma = (const float*)d_in[10];
    const float* beta  = (const float*)d_in[11];
    float* out = (float*)d_out;

    cudaFuncSetAttribute(fused_kernel,
                         cudaFuncAttributeMaxDynamicSharedMemorySize, SMEM_BYTES);

    init_kernel <<<(BB*NN*OUTD + 255)/256, 256>>>(x, wr, wi, w1, w2);
    count_kernel<<<(EE + 255)/256, 256>>>(eidx);
    fused_kernel<<<MROWS/128, 256, SMEM_BYTES>>>(ea, b1, b2, eidx, esh);
    stats_kernel<<<(BB*NN + 255)/256, 256>>>();
    norm_kernel <<<(BB*NN*OUTD + 255)/256, 256>>>(out, gamma, beta);
}